// round 15
// baseline (speedup 1.0000x reference)
#include <cuda_runtime.h>

// SSIM loss, fused single kernel (separable 11-tap Gaussian).
// img1, img2: [16,3,512,512] fp32. Output: scalar mean of SSIM map.
// R15: R10 base (u/d transform, 4 scalar maps, 32x64 tiles, 512 thr, 3 CTAs/SM)
//      with phase-2 octet tasks (8-output window sharing: 592 tasks, 5xLDS.128
//      per task) to cut phase-2 smem load bytes ~40%.

constexpr int IMG_H = 512;
constexpr int IMG_W = 512;
constexpr int NPLANES = 48;              // 16 * 3
constexpr int TILE_W = 32;
constexpr int TILE_H = 64;
constexpr int HALO = 5;
constexpr int IN_W = TILE_W + 2 * HALO;  // 42
constexpr int IN_H = TILE_H + 2 * HALO;  // 74
constexpr int IMG_STRIDE = 44;           // padded row stride, float4-friendly
constexpr int H_STRIDE = 32;             // row stride for H-conv maps
constexpr int MAPSZ = IN_H * H_STRIDE;   // 2368
constexpr int NTHREADS = 512;
constexpr int GRID_X = IMG_W / TILE_W;   // 16
constexpr int GRID_Y = IMG_H / TILE_H;   // 8
constexpr int NBLOCKS = GRID_X * GRID_Y * NPLANES;  // 6144
constexpr int NOCT = IN_H * (TILE_W / 8);           // 296 row-octets
constexpr int NTASK2 = NOCT * 2;                    // 592 phase-2 tasks
constexpr int UDSZ = IN_H * IMG_STRIDE;             // 3256
constexpr int SMEM_FLOATS = 2 * UDSZ + 4 * MAPSZ;   // 15984 (~63.9KB)
constexpr float C1f = 0.0001f;
constexpr float C2f = 0.0009f;

// Gaussian(sigma=1.5) 1D weights, normalized (w2d = outer(g,g))
__device__ constexpr float G[11] = {
    0.00102838f, 0.00759876f, 0.03600077f, 0.10936070f, 0.21300460f,
    0.26601170f,
    0.21300460f, 0.10936070f, 0.03600077f, 0.00759876f, 0.00102838f
};

__device__ float g_partial[NBLOCKS];
__device__ unsigned int g_count;   // starts 0 (BSS), self-resets each call

// 11-tap horizontal conv of an 18-float window -> 8 outputs (weights fold to FFMA-imm)
__device__ __forceinline__ void conv_row8(const float* __restrict__ w, float* __restrict__ acc) {
#pragma unroll
    for (int k = 0; k < 8; k++) {
        float s = 0.f;
#pragma unroll
        for (int j = 0; j < 11; j++) s = fmaf(G[j], w[k + j], s);
        acc[k] = s;
    }
}

__device__ __forceinline__ void load20(const float* __restrict__ src, float* __restrict__ w) {
    const float4* s4 = reinterpret_cast<const float4*>(src);
#pragma unroll
    for (int i = 0; i < 5; i++) {
        float4 v = s4[i];
        w[4 * i + 0] = v.x; w[4 * i + 1] = v.y; w[4 * i + 2] = v.z; w[4 * i + 3] = v.w;
    }
}

__device__ __forceinline__ void store8(float* __restrict__ p, const float* __restrict__ acc) {
    float4* q = reinterpret_cast<float4*>(p);
    q[0] = make_float4(acc[0], acc[1], acc[2], acc[3]);
    q[1] = make_float4(acc[4], acc[5], acc[6], acc[7]);
}

__global__ void __launch_bounds__(NTHREADS, 3)
ssim_main_kernel(const float* __restrict__ img1, const float* __restrict__ img2,
                 float* __restrict__ out) {
    extern __shared__ float sm[];
    float* su = sm;                 // [IN_H][IMG_STRIDE]  u = x + y
    float* sd = sm + UDSZ;          //                      d = x - y
    float* sH = sm + 2 * UDSZ;      // [4][IN_H][H_STRIDE]: cu, cd, cu2, cd2

    const int tid = threadIdx.x;

    // ---- Phase 1: load input tiles as u/d (zero halo at image edges) ----
    // 504 threads: thread = (r0 = tid/42 in 0..11, c = tid%42); rows r0 + 12k.
    if (tid < 504) {
        const int plane = blockIdx.z;
        const int ty = blockIdx.y * TILE_H;
        const int tx = blockIdx.x * TILE_W;
        const float* p1 = img1 + (size_t)plane * IMG_H * IMG_W;
        const float* p2 = img2 + (size_t)plane * IMG_H * IMG_W;
        const int r0 = tid / IN_W;
        const int c = tid - r0 * IN_W;
        const int gx = tx + c - HALO;
        const bool cin = (unsigned)gx < (unsigned)IMG_W;
        const float* c1 = p1 + gx;
        const float* c2 = p2 + gx;
        float* du = su + r0 * IMG_STRIDE + c;
        float* dd = sd + r0 * IMG_STRIDE + c;
#pragma unroll
        for (int k = 0; k < 7; k++) {
            const int r = r0 + 12 * k;
            if (r < IN_H) {
                const int gy = ty + r - HALO;
                float v1 = 0.f, v2 = 0.f;
                if (cin & ((unsigned)gy < (unsigned)IMG_H)) {
                    v1 = __ldg(c1 + gy * IMG_W);
                    v2 = __ldg(c2 + gy * IMG_W);
                }
                du[12 * k * IMG_STRIDE] = v1 + v2;
                dd[12 * k * IMG_STRIDE] = v1 - v2;
            }
        }
    }
    __syncthreads();

    // ---- Phase 2: horizontal conv, octet tasks (window shared over 8 outputs).
    // Task = (row-octet, group). group 0: cu+cu2 from su; group 1: cd+cd2 from sd.
    // 592 tasks / 512 threads; per task: 5 LDS.128 + 176 FFMA + 18 FMUL + 4 STS.128.
    for (int t = tid; t < NTASK2; t += NTHREADS) {
        int ro = t;
        int goff = 0;
        if (ro >= NOCT) { ro -= NOCT; goff = 1; }
        const int r = ro >> 2;                // 4 octets per row
        const int c0 = (ro & 3) << 3;         // 0, 8, 16, 24
        const float* src = su + goff * UDSZ + r * IMG_STRIDE + c0;
        float* hrow = sH + goff * MAPSZ + r * H_STRIDE + c0;
        float w[20], acc[8];
        load20(src, w);
        conv_row8(w, acc);                                    // cu or cd
        store8(hrow, acc);
#pragma unroll
        for (int i = 0; i < 18; i++) w[i] = w[i] * w[i];
        conv_row8(w, acc);                                    // cu2 or cd2
        store8(hrow + 2 * MAPSZ, acc);
    }
    __syncthreads();

    // ---- Phase 3: vertical conv (4-row strip per thread, exactly 512 tasks) ----
    float lsum = 0.f;
    {
        const int c = tid & 31;
        const int r0 = (tid >> 5) * 4;                // 16 strips of 4 rows
        float a0[4], a1[4], a2[4], a3[4];             // cu, cd, cu2, cd2
#pragma unroll
        for (int k = 0; k < 4; k++) { a0[k] = 0.f; a1[k] = 0.f; a2[k] = 0.f; a3[k] = 0.f; }
        const float* h0 = sH + r0 * H_STRIDE + c;
#pragma unroll
        for (int i = 0; i < 14; i++) {
            float v0 = h0[i * H_STRIDE + 0 * MAPSZ];
            float v1 = h0[i * H_STRIDE + 1 * MAPSZ];
            float v2 = h0[i * H_STRIDE + 2 * MAPSZ];
            float v3 = h0[i * H_STRIDE + 3 * MAPSZ];
#pragma unroll
            for (int ro = 0; ro < 4; ro++) {
                const int j = i - ro;
                if (j >= 0 && j < 11) {               // compile-time resolved
                    a0[ro] = fmaf(G[j], v0, a0[ro]);
                    a1[ro] = fmaf(G[j], v1, a1[ro]);
                    a2[ro] = fmaf(G[j], v2, a2[ro]);
                    a3[ro] = fmaf(G[j], v3, a3[ro]);
                }
            }
        }
#pragma unroll
        for (int ro = 0; ro < 4; ro++) {
            float cu = a0[ro], cd = a1[ro], cu2 = a2[ro], cd2 = a3[ro];
            float A = cu * cu;                                 // (mu1+mu2)^2
            float B = cd * cd;                                 // (mu1-mu2)^2
            float t1 = 0.5f * (A - B) + C1f;                   // 2*mu1*mu2 + C1
            float t2 = 0.5f * ((cu2 - cd2) - (A - B)) + C2f;   // 2*sigma12 + C2
            float t3 = 0.5f * (A + B) + C1f;                   // mu1^2+mu2^2 + C1
            float t4 = 0.5f * ((cu2 + cd2) - (A + B)) + C2f;   // sx+sy + C2
            lsum += __fdividef(t1 * t2, t3 * t4);
        }
    }

    // ---- Block reduce (fp32) ----
    __shared__ float wsum[NTHREADS / 32];
#pragma unroll
    for (int o = 16; o > 0; o >>= 1) lsum += __shfl_xor_sync(0xFFFFFFFFu, lsum, o);
    if ((tid & 31) == 0) wsum[tid >> 5] = lsum;
    __syncthreads();

    __shared__ bool isLast;
    if (tid == 0) {
        const int bid = (blockIdx.z * GRID_Y + blockIdx.y) * GRID_X + blockIdx.x;
        float s = 0.f;
#pragma unroll
        for (int i = 0; i < NTHREADS / 32; i++) s += wsum[i];
        g_partial[bid] = s;
        __threadfence();
        unsigned int old = atomicAdd(&g_count, 1u);
        isLast = (old == (unsigned)(NBLOCKS - 1));
    }
    __syncthreads();

    // ---- Last block: final reduction in double ----
    if (isLast) {
        double d = 0.0;
        for (int k = 0; k < NBLOCKS / NTHREADS; k++)
            d += (double)g_partial[tid + k * NTHREADS];
#pragma unroll
        for (int o = 16; o > 0; o >>= 1) d += __shfl_xor_sync(0xFFFFFFFFu, d, o);
        __shared__ double dsum[NTHREADS / 32];
        if ((tid & 31) == 0) dsum[tid >> 5] = d;
        __syncthreads();
        if (tid == 0) {
            double s = 0.0;
#pragma unroll
            for (int i = 0; i < NTHREADS / 32; i++) s += dsum[i];
            out[0] = (float)(s / (double)((size_t)NPLANES * IMG_H * IMG_W));
            g_count = 0;   // self-reset for next graph replay
        }
    }
}

extern "C" void kernel_launch(void* const* d_in, const int* in_sizes, int n_in,
                              void* d_out, int out_size) {
    const float* img1 = (const float*)d_in[0];
    const float* img2 = (const float*)d_in[1];
    float* out = (float*)d_out;

    cudaFuncSetAttribute(ssim_main_kernel,
                         cudaFuncAttributeMaxDynamicSharedMemorySize,
                         SMEM_FLOATS * (int)sizeof(float));

    dim3 grid(GRID_X, GRID_Y, NPLANES);
    ssim_main_kernel<<<grid, NTHREADS, SMEM_FLOATS * sizeof(float)>>>(img1, img2, out);
}

// round 16
// speedup vs baseline: 1.0226x; 1.0226x over previous
#include <cuda_runtime.h>

// SSIM loss, fused single kernel (separable 11-tap Gaussian).
// img1, img2: [16,3,512,512] fp32. Output: scalar mean of SSIM map.
// R16: R15 base (u/d transform, 4 scalar maps, 32x64 tiles, 512 thr, 3 CTAs/SM,
//      octet phase-2 tasks) + phase-1 guard specialization:
//      unguarded interior-block path, compile-time row-count split.

constexpr int IMG_H = 512;
constexpr int IMG_W = 512;
constexpr int NPLANES = 48;              // 16 * 3
constexpr int TILE_W = 32;
constexpr int TILE_H = 64;
constexpr int HALO = 5;
constexpr int IN_W = TILE_W + 2 * HALO;  // 42
constexpr int IN_H = TILE_H + 2 * HALO;  // 74
constexpr int IMG_STRIDE = 44;           // padded row stride, float4-friendly
constexpr int H_STRIDE = 32;             // row stride for H-conv maps
constexpr int MAPSZ = IN_H * H_STRIDE;   // 2368
constexpr int NTHREADS = 512;
constexpr int GRID_X = IMG_W / TILE_W;   // 16
constexpr int GRID_Y = IMG_H / TILE_H;   // 8
constexpr int NBLOCKS = GRID_X * GRID_Y * NPLANES;  // 6144
constexpr int NOCT = IN_H * (TILE_W / 8);           // 296 row-octets
constexpr int NTASK2 = NOCT * 2;                    // 592 phase-2 tasks
constexpr int UDSZ = IN_H * IMG_STRIDE;             // 3256
constexpr int SMEM_FLOATS = 2 * UDSZ + 4 * MAPSZ;   // 15984 (~63.9KB)
constexpr float C1f = 0.0001f;
constexpr float C2f = 0.0009f;

// Gaussian(sigma=1.5) 1D weights, normalized (w2d = outer(g,g))
__device__ constexpr float G[11] = {
    0.00102838f, 0.00759876f, 0.03600077f, 0.10936070f, 0.21300460f,
    0.26601170f,
    0.21300460f, 0.10936070f, 0.03600077f, 0.00759876f, 0.00102838f
};

__device__ float g_partial[NBLOCKS];
__device__ unsigned int g_count;   // starts 0 (BSS), self-resets each call

// 11-tap horizontal conv of an 18-float window -> 8 outputs (weights fold to FFMA-imm)
__device__ __forceinline__ void conv_row8(const float* __restrict__ w, float* __restrict__ acc) {
#pragma unroll
    for (int k = 0; k < 8; k++) {
        float s = 0.f;
#pragma unroll
        for (int j = 0; j < 11; j++) s = fmaf(G[j], w[k + j], s);
        acc[k] = s;
    }
}

__device__ __forceinline__ void load20(const float* __restrict__ src, float* __restrict__ w) {
    const float4* s4 = reinterpret_cast<const float4*>(src);
#pragma unroll
    for (int i = 0; i < 5; i++) {
        float4 v = s4[i];
        w[4 * i + 0] = v.x; w[4 * i + 1] = v.y; w[4 * i + 2] = v.z; w[4 * i + 3] = v.w;
    }
}

__device__ __forceinline__ void store8(float* __restrict__ p, const float* __restrict__ acc) {
    float4* q = reinterpret_cast<float4*>(p);
    q[0] = make_float4(acc[0], acc[1], acc[2], acc[3]);
    q[1] = make_float4(acc[4], acc[5], acc[6], acc[7]);
}

__global__ void __launch_bounds__(NTHREADS, 3)
ssim_main_kernel(const float* __restrict__ img1, const float* __restrict__ img2,
                 float* __restrict__ out) {
    extern __shared__ float sm[];
    float* su = sm;                 // [IN_H][IMG_STRIDE]  u = x + y
    float* sd = sm + UDSZ;          //                      d = x - y
    float* sH = sm + 2 * UDSZ;      // [4][IN_H][H_STRIDE]: cu, cd, cu2, cd2

    const int tid = threadIdx.x;

    // ---- Phase 1: load input tiles as u/d.
    // 504 threads: thread = (r0 = tid/42 in 0..11, c = tid%42).
    // Rows r0 + 12k: k=0..5 for all threads (rows 0..71); threads r0<2 add row r0+72.
    // Interior blocks (65.6%) take a fully unguarded path.
    if (tid < 504) {
        const int plane = blockIdx.z;
        const int ty = blockIdx.y * TILE_H;
        const int tx = blockIdx.x * TILE_W;
        const float* p1 = img1 + (size_t)plane * IMG_H * IMG_W;
        const float* p2 = img2 + (size_t)plane * IMG_H * IMG_W;
        const int r0 = tid / IN_W;
        const int c = tid - r0 * IN_W;
        const int gx = tx + c - HALO;
        float* du = su + r0 * IMG_STRIDE + c;
        float* dd = sd + r0 * IMG_STRIDE + c;
        const bool interior =
            (blockIdx.x > 0) & (blockIdx.x < GRID_X - 1) &
            (blockIdx.y > 0) & (blockIdx.y < GRID_Y - 1);
        if (interior) {
            const float* a1 = p1 + (ty + r0 - HALO) * IMG_W + gx;
            const float* a2 = p2 + (ty + r0 - HALO) * IMG_W + gx;
#pragma unroll
            for (int k = 0; k < 6; k++) {
                float v1 = __ldg(a1 + 12 * k * IMG_W);
                float v2 = __ldg(a2 + 12 * k * IMG_W);
                du[12 * k * IMG_STRIDE] = v1 + v2;
                dd[12 * k * IMG_STRIDE] = v1 - v2;
            }
            if (r0 < 2) {
                float v1 = __ldg(a1 + 72 * IMG_W);
                float v2 = __ldg(a2 + 72 * IMG_W);
                du[72 * IMG_STRIDE] = v1 + v2;
                dd[72 * IMG_STRIDE] = v1 - v2;
            }
        } else {
            const bool cin = (unsigned)gx < (unsigned)IMG_W;
            const float* c1 = p1 + gx;
            const float* c2 = p2 + gx;
#pragma unroll
            for (int k = 0; k < 6; k++) {
                const int gy = ty + r0 + 12 * k - HALO;
                float v1 = 0.f, v2 = 0.f;
                if (cin & ((unsigned)gy < (unsigned)IMG_H)) {
                    v1 = __ldg(c1 + gy * IMG_W);
                    v2 = __ldg(c2 + gy * IMG_W);
                }
                du[12 * k * IMG_STRIDE] = v1 + v2;
                dd[12 * k * IMG_STRIDE] = v1 - v2;
            }
            if (r0 < 2) {
                const int gy = ty + r0 + 72 - HALO;
                float v1 = 0.f, v2 = 0.f;
                if (cin & ((unsigned)gy < (unsigned)IMG_H)) {
                    v1 = __ldg(c1 + gy * IMG_W);
                    v2 = __ldg(c2 + gy * IMG_W);
                }
                du[72 * IMG_STRIDE] = v1 + v2;
                dd[72 * IMG_STRIDE] = v1 - v2;
            }
        }
    }
    __syncthreads();

    // ---- Phase 2: horizontal conv, octet tasks (window shared over 8 outputs).
    // Task = (row-octet, group). group 0: cu+cu2 from su; group 1: cd+cd2 from sd.
    // 592 tasks / 512 threads.
    for (int t = tid; t < NTASK2; t += NTHREADS) {
        int ro = t;
        int goff = 0;
        if (ro >= NOCT) { ro -= NOCT; goff = 1; }
        const int r = ro >> 2;                // 4 octets per row
        const int c0 = (ro & 3) << 3;         // 0, 8, 16, 24
        const float* src = su + goff * UDSZ + r * IMG_STRIDE + c0;
        float* hrow = sH + goff * MAPSZ + r * H_STRIDE + c0;
        float w[20], acc[8];
        load20(src, w);
        conv_row8(w, acc);                                    // cu or cd
        store8(hrow, acc);
#pragma unroll
        for (int i = 0; i < 18; i++) w[i] = w[i] * w[i];
        conv_row8(w, acc);                                    // cu2 or cd2
        store8(hrow + 2 * MAPSZ, acc);
    }
    __syncthreads();

    // ---- Phase 3: vertical conv (4-row strip per thread, exactly 512 tasks) ----
    float lsum = 0.f;
    {
        const int c = tid & 31;
        const int r0 = (tid >> 5) * 4;                // 16 strips of 4 rows
        float a0[4], a1[4], a2[4], a3[4];             // cu, cd, cu2, cd2
#pragma unroll
        for (int k = 0; k < 4; k++) { a0[k] = 0.f; a1[k] = 0.f; a2[k] = 0.f; a3[k] = 0.f; }
        const float* h0 = sH + r0 * H_STRIDE + c;
#pragma unroll
        for (int i = 0; i < 14; i++) {
            float v0 = h0[i * H_STRIDE + 0 * MAPSZ];
            float v1 = h0[i * H_STRIDE + 1 * MAPSZ];
            float v2 = h0[i * H_STRIDE + 2 * MAPSZ];
            float v3 = h0[i * H_STRIDE + 3 * MAPSZ];
#pragma unroll
            for (int ro = 0; ro < 4; ro++) {
                const int j = i - ro;
                if (j >= 0 && j < 11) {               // compile-time resolved
                    a0[ro] = fmaf(G[j], v0, a0[ro]);
                    a1[ro] = fmaf(G[j], v1, a1[ro]);
                    a2[ro] = fmaf(G[j], v2, a2[ro]);
                    a3[ro] = fmaf(G[j], v3, a3[ro]);
                }
            }
        }
#pragma unroll
        for (int ro = 0; ro < 4; ro++) {
            float cu = a0[ro], cd = a1[ro], cu2 = a2[ro], cd2 = a3[ro];
            float A = cu * cu;                                 // (mu1+mu2)^2
            float B = cd * cd;                                 // (mu1-mu2)^2
            float t1 = 0.5f * (A - B) + C1f;                   // 2*mu1*mu2 + C1
            float t2 = 0.5f * ((cu2 - cd2) - (A - B)) + C2f;   // 2*sigma12 + C2
            float t3 = 0.5f * (A + B) + C1f;                   // mu1^2+mu2^2 + C1
            float t4 = 0.5f * ((cu2 + cd2) - (A + B)) + C2f;   // sx+sy + C2
            lsum += __fdividef(t1 * t2, t3 * t4);
        }
    }

    // ---- Block reduce (fp32) ----
    __shared__ float wsum[NTHREADS / 32];
#pragma unroll
    for (int o = 16; o > 0; o >>= 1) lsum += __shfl_xor_sync(0xFFFFFFFFu, lsum, o);
    if ((tid & 31) == 0) wsum[tid >> 5] = lsum;
    __syncthreads();

    __shared__ bool isLast;
    if (tid == 0) {
        const int bid = (blockIdx.z * GRID_Y + blockIdx.y) * GRID_X + blockIdx.x;
        float s = 0.f;
#pragma unroll
        for (int i = 0; i < NTHREADS / 32; i++) s += wsum[i];
        g_partial[bid] = s;
        __threadfence();
        unsigned int old = atomicAdd(&g_count, 1u);
        isLast = (old == (unsigned)(NBLOCKS - 1));
    }
    __syncthreads();

    // ---- Last block: final reduction in double ----
    if (isLast) {
        double d = 0.0;
        for (int k = 0; k < NBLOCKS / NTHREADS; k++)
            d += (double)g_partial[tid + k * NTHREADS];
#pragma unroll
        for (int o = 16; o > 0; o >>= 1) d += __shfl_xor_sync(0xFFFFFFFFu, d, o);
        __shared__ double dsum[NTHREADS / 32];
        if ((tid & 31) == 0) dsum[tid >> 5] = d;
        __syncthreads();
        if (tid == 0) {
            double s = 0.0;
#pragma unroll
            for (int i = 0; i < NTHREADS / 32; i++) s += dsum[i];
            out[0] = (float)(s / (double)((size_t)NPLANES * IMG_H * IMG_W));
            g_count = 0;   // self-reset for next graph replay
        }
    }
}

extern "C" void kernel_launch(void* const* d_in, const int* in_sizes, int n_in,
                              void* d_out, int out_size) {
    const float* img1 = (const float*)d_in[0];
    const float* img2 = (const float*)d_in[1];
    float* out = (float*)d_out;

    cudaFuncSetAttribute(ssim_main_kernel,
                         cudaFuncAttributeMaxDynamicSharedMemorySize,
                         SMEM_FLOATS * (int)sizeof(float));

    dim3 grid(GRID_X, GRID_Y, NPLANES);
    ssim_main_kernel<<<grid, NTHREADS, SMEM_FLOATS * sizeof(float)>>>(img1, img2, out);
}